// round 12
// baseline (speedup 1.0000x reference)
#include <cuda_runtime.h>
#include <cuda_bf16.h>
#include <cstdint>

#define LREF  1024
#define FEA   1028
#define MEMD  50
#define KPAD  64
#define DATED 32
#define MAXB  32768
#define NTILE (MAXB / 128)

// ------------------- device scratch (allocation-free rule) -------------------
__device__ __nv_bfloat16 g_atth[MAXB * KPAD];   // att hi  [row][k] padded
__device__ __nv_bfloat16 g_attl[MAXB * KPAD];   // att lo
__device__ __nv_bfloat16 g_Bh[LREF * KPAD];     // Wfold^T hi [col][k]
__device__ __nv_bfloat16 g_Bl[LREF * KPAD];     // Wfold^T lo
__device__ float         g_wt[MAXB];            // gate weight per row
__device__ float         g_bs[MAXB];            // gate bias   per row
__device__ int           g_flag[NTILE];         // per-128-row-tile gate-done flag

// ------------------- helpers -------------------
__device__ __forceinline__ uint32_t smem_u32(const void* p) {
    uint32_t a;
    asm("{ .reg .u64 t; cvta.to.shared.u64 t, %1; cvt.u32.u64 %0, t; }" : "=r"(a) : "l"(p));
    return a;
}
__device__ __forceinline__ void ldsm_x4(uint32_t* r, uint32_t a) {
    asm volatile("ldmatrix.sync.aligned.m8n8.x4.shared.b16 {%0,%1,%2,%3}, [%4];"
                 : "=r"(r[0]), "=r"(r[1]), "=r"(r[2]), "=r"(r[3]) : "r"(a));
}
__device__ __forceinline__ void mma_bf16(float* d, const uint32_t* a, const uint32_t* b) {
    asm volatile(
        "mma.sync.aligned.m16n8k16.row.col.f32.bf16.bf16.f32 "
        "{%0,%1,%2,%3}, {%4,%5,%6,%7}, {%8,%9}, {%0,%1,%2,%3};"
        : "+f"(d[0]), "+f"(d[1]), "+f"(d[2]), "+f"(d[3])
        : "r"(a[0]), "r"(a[1]), "r"(a[2]), "r"(a[3]), "r"(b[0]), "r"(b[1]));
}
__device__ __forceinline__ void cp16(uint32_t dst, const void* src) {
    asm volatile("cp.async.cg.shared.global [%0], [%1], 16;" :: "r"(dst), "l"(src) : "memory");
}
#define CP_COMMIT() asm volatile("cp.async.commit_group;" ::: "memory")
#define CP_WAIT(n)  asm volatile("cp.async.wait_group %0;" :: "n"(n) : "memory")

__device__ __forceinline__ int ld_relaxed(const int* p) {
    int v;
    asm volatile("ld.relaxed.gpu.b32 %0, [%1];" : "=r"(v) : "l"(p) : "memory");
    return v;
}
__device__ __forceinline__ void st_release(int* p, int v) {
    asm volatile("st.release.gpu.b32 [%0], %1;" :: "l"(p), "r"(v) : "memory");
}
#define FENCE_ACQ() asm volatile("fence.acq_rel.gpu;" ::: "memory")

// XOR swizzle for 128B-row tiles: conflict-free ldmatrix + conflict-free stores
__device__ __forceinline__ uint32_t swz(uint32_t r, uint32_t c) {
    return r * 128u + (c ^ ((r & 7u) << 4));
}

// fused-kernel smem layout (bytes)
#define OFF_FCW 0                       // 4KB
#define OFF_FCB 4096                    // 4KB
#define OFF_B   8192                    // resident B tile hi+lo, 32KB
#define OFF_A   40960                   // 2 bufs x 32KB
#define SMEM_SZ (OFF_A + 2 * 32768)     // 106496 -> occ 2 (212992/SM)

#define MAIN_SLOTS 37                   // 8 cb * 37 = 296 = 2*148 CTAs

// ---------------------------------------------------------------------------
// k_prep: att (Bn/256 blocks) + wconv (256 blocks) + flag reset
// ---------------------------------------------------------------------------
__global__ __launch_bounds__(256) void k_prep(const float* __restrict__ mem_W,
                                              const float* __restrict__ convt_w,
                                              const float* __restrict__ dv,
                                              const float* __restrict__ dW, int Bn) {
    int t = threadIdx.x;
    const int attBlocks = Bn / 256;

    if ((int)blockIdx.x >= attBlocks) {
        // ---------------- wconv + flag reset ----------------
        int lb = blockIdx.x - attBlocks;
        if (lb == 0 && t < Bn / 128) g_flag[t] = 0;
        int i = lb * 256 + t;
        int c = i >> 6, k = i & 63;
        float s = 0.f;
        if (k < MEMD) {
            float w0 = convt_w[4], w1 = convt_w[3], w2 = convt_w[2], w3 = convt_w[1], w4 = convt_w[0];
            const float* p = mem_W + k * FEA + c;
            s = p[0]*w0 + p[1]*w1 + p[2]*w2 + p[3]*w3 + p[4]*w4;
        }
        __nv_bfloat16 h = __float2bfloat16_rn(s);
        __nv_bfloat16 l = __float2bfloat16_rn(s - __bfloat162float(h));
        g_Bh[i] = h;
        g_Bl[i] = l;
        return;
    }

    // ---------------- att ----------------
    __shared__ float s_dv[256][DATED + 1];
    __shared__ float s_dW[MEMD][DATED];
    __shared__ float s_out[256][MEMD + 1];

    int base = blockIdx.x * 256;

    for (int i = t; i < MEMD * DATED; i += 256) s_dW[i / DATED][i % DATED] = dW[i];
    for (int i = t; i < 256 * DATED; i += 256)
        s_dv[i / DATED][i % DATED] = dv[(size_t)base * DATED + i];
    __syncthreads();

    float sc[MEMD];
    float mx = -1e30f;
    #pragma unroll
    for (int m = 0; m < MEMD; m++) {
        float s = 0.f;
        #pragma unroll
        for (int d = 0; d < DATED; d++) s += s_dv[t][d] * s_dW[m][d];
        sc[m] = s;
        mx = fmaxf(mx, s);
    }
    float se = 0.f;
    #pragma unroll
    for (int m = 0; m < MEMD; m++) { float e = __expf(sc[m] - mx); sc[m] = e; se += e; }
    float inv = 1.f / se;
    float s2 = 0.f;
    #pragma unroll
    for (int m = 0; m < MEMD; m++) {
        float a = sc[m] * inv;
        float d = a - 0.0025f;
        float v = fmaxf(d, 0.f) * a / (fabsf(d) + 1e-12f);
        sc[m] = v;
        s2 += fabsf(v);
    }
    float inv2 = 1.f / (s2 + 1e-12f);
    #pragma unroll
    for (int m = 0; m < MEMD; m++) s_out[t][m] = sc[m] * inv2;
    __syncthreads();

    for (int i = t; i < 256 * KPAD; i += 256) {
        int r = i >> 6, k = i & 63;
        float a = (k < MEMD) ? s_out[r][k] : 0.f;
        __nv_bfloat16 h = __float2bfloat16_rn(a);
        __nv_bfloat16 l = __float2bfloat16_rn(a - __bfloat162float(h));
        size_t gi = (size_t)base * KPAD + i;
        g_atth[gi] = h;
        g_attl[gi] = l;
    }
}

// ---------------------------------------------------------------------------
// stage one A row-tile (hi+lo, 32KB) into smem buffer via cp.async
// ---------------------------------------------------------------------------
__device__ __forceinline__ void stage_A(uint32_t sb, int tile, int buf, int t) {
    #pragma unroll
    for (int j = 0; j < 8; j++) {
        int i = t + j * 256;
        int term = i >> 10, rem = i & 1023, r = rem >> 3, ch = rem & 7;
        const __nv_bfloat16* src =
            (term ? g_attl : g_atth) + (size_t)(tile * 128 + r) * KPAD + ch * 8;
        cp16(sb + OFF_A + buf * 32768 + term * 16384 + swz((uint32_t)r, (uint32_t)(ch * 16)), src);
    }
}

// ---------------------------------------------------------------------------
// k_fused: 296 persistent CTAs; cb = blk&7, slot = blk>>3.
// Tile T handled at the same iteration by the 8 CTAs of slot T%37; the one
// with cb == T%8 computes gates(T) first (flag), others MMA then acquire.
// ---------------------------------------------------------------------------
__global__ __launch_bounds__(256, 2) void k_fused(const float* __restrict__ x,
                                                  const float* __restrict__ fcw,
                                                  const float* __restrict__ fcwb,
                                                  const float* __restrict__ fcb,
                                                  const float* __restrict__ fcbb,
                                                  float* __restrict__ out, int Bn) {
    extern __shared__ char smem[];
    const uint32_t sb = smem_u32(smem);
    const int t = threadIdx.x;
    const int warp = t >> 5, lane = t & 31;
    const int nTiles = Bn / 128;

    const int cb   = blockIdx.x & 7;
    const int slot = blockIdx.x >> 3;

    // stage: fc weights + resident B tile + first A tile (one group)
    cp16(sb + OFF_FCW + t * 16, fcw + t * 4);
    cp16(sb + OFF_FCB + t * 16, fcb + t * 4);
    #pragma unroll
    for (int j = 0; j < 8; j++) {
        int i = t + j * 256;
        int term = i >> 10, rem = i & 1023, r = rem >> 3, ch = rem & 7;
        const __nv_bfloat16* src =
            (term ? g_Bl : g_Bh) + (size_t)(cb * 128 + r) * KPAD + ch * 8;
        cp16(sb + OFF_B + term * 16384 + swz((uint32_t)r, (uint32_t)(ch * 16)), src);
    }
    if (slot < nTiles) stage_A(sb, slot, 0, t);
    CP_COMMIT();

    // per-lane fragment constants
    const int grp = lane >> 2, qc = lane & 3;
    const uint32_t rb  = (uint32_t)((lane & 7) + ((lane >> 4) << 3));
    const uint32_t ccb = (uint32_t)(((lane >> 3) & 1) * 16);
    const uint32_t xv  = (uint32_t)((lane & 7) << 4);
    const uint32_t ra    = (uint32_t)(warp * 16 + (lane & 15));
    const uint32_t cbase = (uint32_t)((lane >> 4) * 16);

    const float fwb = fcwb[0], fbb = fcbb[0];

    int buf = 0;
    for (int tile = slot; tile < nTiles; tile += MAIN_SLOTS) {
        CP_WAIT(0);              // staged data for this tile ready
        __syncthreads();

        // A fragments -> registers
        uint32_t ah[4][4], al[4][4];
        const uint32_t abase = sb + OFF_A + (uint32_t)(buf * 32768);
        #pragma unroll
        for (int ks = 0; ks < 4; ks++) {
            uint32_t off = swz(ra, cbase + ks * 32);
            ldsm_x4(ah[ks], abase + off);
            ldsm_x4(al[ks], abase + 16384 + off);
        }
        __syncthreads();         // all warps got A -> other buf may be overwritten

        if (tile + MAIN_SLOTS < nTiles) stage_A(sb, tile + MAIN_SLOTS, buf ^ 1, t);
        CP_COMMIT();

        const bool producer = (cb == (tile & 7));

        // ---- producer: compute gates for this tile's 128 rows, set flag ----
        if (producer) {
            const float4* fw4 = (const float4*)(smem + OFF_FCW);
            const float4* fb4 = (const float4*)(smem + OFF_FCB);
            int rowBase = tile * 128;
            #pragma unroll 1
            for (int rr = 0; rr < 8; rr++) {
                int r0 = warp * 16 + rr * 2;
                const float4* x0 = (const float4*)(x + (size_t)(rowBase + r0) * LREF);
                const float4* x1 = (const float4*)(x + (size_t)(rowBase + r0 + 1) * LREF);
                float dw0 = 0.f, db0 = 0.f, dw1 = 0.f, db1 = 0.f;
                #pragma unroll
                for (int j = 0; j < 8; j++) {
                    float4 v0 = x0[lane + 32 * j];
                    float4 v1 = x1[lane + 32 * j];
                    float4 a = fw4[lane + 32 * j];
                    float4 b = fb4[lane + 32 * j];
                    dw0 += v0.x*a.x + v0.y*a.y + v0.z*a.z + v0.w*a.w;
                    db0 += v0.x*b.x + v0.y*b.y + v0.z*b.z + v0.w*b.w;
                    dw1 += v1.x*a.x + v1.y*a.y + v1.z*a.z + v1.w*a.w;
                    db1 += v1.x*b.x + v1.y*b.y + v1.z*b.z + v1.w*b.w;
                }
                #pragma unroll
                for (int o = 16; o; o >>= 1) {
                    dw0 += __shfl_xor_sync(0xffffffffu, dw0, o);
                    db0 += __shfl_xor_sync(0xffffffffu, db0, o);
                    dw1 += __shfl_xor_sync(0xffffffffu, dw1, o);
                    db1 += __shfl_xor_sync(0xffffffffu, db1, o);
                }
                if (lane == 0) {
                    int row = rowBase + r0;
                    float wt = tanhf(dw0 + fwb) * 0.5f + 1.0f;
                    float bs = tanhf(db0 + fbb) * 0.5f;
                    g_wt[row] = wt;  g_bs[row] = bs;
                    out[(size_t)Bn * LREF + row]      = wt;
                    out[(size_t)Bn * LREF + Bn + row] = bs;
                    wt = tanhf(dw1 + fwb) * 0.5f + 1.0f;
                    bs = tanhf(db1 + fbb) * 0.5f;
                    g_wt[row + 1] = wt;  g_bs[row + 1] = bs;
                    out[(size_t)Bn * LREF + row + 1]      = wt;
                    out[(size_t)Bn * LREF + Bn + row + 1] = bs;
                }
            }
            __syncthreads();
            __threadfence();
            if (t == 0) st_release(&g_flag[tile], 1);
        }

        // ---- MMA: 128 rows x 128 cols, 3-term bf16 split ----
        float acc[16][4];
        #pragma unroll
        for (int nt = 0; nt < 16; nt++) {
            acc[nt][0] = 0.f; acc[nt][1] = 0.f; acc[nt][2] = 0.f; acc[nt][3] = 0.f;
        }
        #pragma unroll
        for (int ks = 0; ks < 4; ks++) {
            const uint32_t col = (ccb + (uint32_t)(ks * 32)) ^ xv;
            #pragma unroll
            for (int ntp = 0; ntp < 8; ntp++) {
                uint32_t addr = sb + OFF_B + (uint32_t)((ntp * 16) + rb) * 128u + col;
                uint32_t bh[4], bl[4];
                ldsm_x4(bh, addr);
                ldsm_x4(bl, addr + 16384);
                mma_bf16(acc[2*ntp],     ah[ks], bh);
                mma_bf16(acc[2*ntp + 1], ah[ks], bh + 2);
                mma_bf16(acc[2*ntp],     al[ks], bh);
                mma_bf16(acc[2*ntp + 1], al[ks], bh + 2);
                mma_bf16(acc[2*ntp],     ah[ks], bl);
                mma_bf16(acc[2*ntp + 1], ah[ks], bl + 2);
            }
        }

        // ---- consumers: acquire gates(tile); visible to all lanes ----
        if (!producer) {
            if (lane == 0) {
                while (ld_relaxed(&g_flag[tile]) == 0) __nanosleep(64);
            }
            __syncwarp();
            FENCE_ACQ();
        }

        // ---- fused epilogue ----
        {
            int row0 = tile * 128 + warp * 16 + grp;
            float wt0 = g_wt[row0],     bs0 = g_bs[row0];
            float wt1 = g_wt[row0 + 8], bs1 = g_bs[row0 + 8];
            size_t r0 = (size_t)row0 * LREF;
            size_t r1 = r0 + 8 * LREF;
            int colBase = cb * 128 + qc * 2;
            #pragma unroll
            for (int nt = 0; nt < 16; nt++) {
                int col = colBase + nt * 8;
                *(float2*)&out[r0 + col] =
                    make_float2(acc[nt][0] * wt0 + bs0, acc[nt][1] * wt0 + bs0);
                *(float2*)&out[r1 + col] =
                    make_float2(acc[nt][2] * wt1 + bs1, acc[nt][3] * wt1 + bs1);
            }
        }
        buf ^= 1;
    }
}

// ---------------------------------------------------------------------------
extern "C" void kernel_launch(void* const* d_in, const int* in_sizes, int n_in,
                              void* d_out, int out_size) {
    const float* x    = (const float*)d_in[0];
    const float* dv   = (const float*)d_in[1];
    // d_in[2] = conv_w (dead in reference)
    const float* ctw  = (const float*)d_in[3];
    const float* memW = (const float*)d_in[4];
    const float* dW   = (const float*)d_in[5];
    const float* fcw  = (const float*)d_in[6];
    const float* fcwb = (const float*)d_in[7];
    const float* fcb  = (const float*)d_in[8];
    const float* fcbb = (const float*)d_in[9];
    float* out = (float*)d_out;

    int Bn = in_sizes[0] / LREF;

    cudaFuncSetAttribute(k_fused, cudaFuncAttributeMaxDynamicSharedMemorySize, SMEM_SZ);

    k_prep<<<Bn / 256 + 256, 256>>>(memW, ctw, dv, dW, Bn);
    k_fused<<<8 * MAIN_SLOTS, 256, SMEM_SZ>>>(x, fcw, fcwb, fcb, fcbb, out, Bn);
}

// round 13
// speedup vs baseline: 3.3994x; 3.3994x over previous
#include <cuda_runtime.h>
#include <cuda_bf16.h>
#include <cstdint>

#define LREF  1024
#define FEA   1028
#define MEMD  50
#define KPAD  64
#define DATED 32
#define MAXB  32768

// ------------------- device scratch (allocation-free rule) -------------------
__device__ __nv_bfloat16 g_atth[MAXB * KPAD];   // att hi  [row][k] padded
__device__ __nv_bfloat16 g_attl[MAXB * KPAD];   // att lo
__device__ __nv_bfloat16 g_Bh[LREF * KPAD];     // Wfold^T hi [col][k]
__device__ __nv_bfloat16 g_Bl[LREF * KPAD];     // Wfold^T lo

// ------------------- helpers -------------------
__device__ __forceinline__ uint32_t smem_u32(const void* p) {
    uint32_t a;
    asm("{ .reg .u64 t; cvta.to.shared.u64 t, %1; cvt.u32.u64 %0, t; }" : "=r"(a) : "l"(p));
    return a;
}
__device__ __forceinline__ void ldsm_x4(uint32_t* r, uint32_t a) {
    asm volatile("ldmatrix.sync.aligned.m8n8.x4.shared.b16 {%0,%1,%2,%3}, [%4];"
                 : "=r"(r[0]), "=r"(r[1]), "=r"(r[2]), "=r"(r[3]) : "r"(a));
}
__device__ __forceinline__ void mma_bf16(float* d, const uint32_t* a, const uint32_t* b) {
    asm volatile(
        "mma.sync.aligned.m16n8k16.row.col.f32.bf16.bf16.f32 "
        "{%0,%1,%2,%3}, {%4,%5,%6,%7}, {%8,%9}, {%0,%1,%2,%3};"
        : "+f"(d[0]), "+f"(d[1]), "+f"(d[2]), "+f"(d[3])
        : "r"(a[0]), "r"(a[1]), "r"(a[2]), "r"(a[3]), "r"(b[0]), "r"(b[1]));
}
__device__ __forceinline__ void cp16(uint32_t dst, const void* src) {
    asm volatile("cp.async.cg.shared.global [%0], [%1], 16;" :: "r"(dst), "l"(src) : "memory");
}
#define CP_COMMIT() asm volatile("cp.async.commit_group;" ::: "memory")
#define CP_WAIT(n)  asm volatile("cp.async.wait_group %0;" :: "n"(n) : "memory")

// XOR swizzle for 128B-row tiles: conflict-free ldmatrix + conflict-free stores
__device__ __forceinline__ uint32_t swz(uint32_t r, uint32_t c) {
    return r * 128u + (c ^ ((r & 7u) << 4));
}

// k_main smem layout (bytes)
#define OFF_WT  0                       // 512B
#define OFF_BS  512                     // 512B
#define OFF_A   1024                    // hi 16KB + lo 16KB
#define OFF_B   33792                   // 2 bufs x (hi 16KB + lo 16KB)
#define SMEM_SZ (OFF_B + 65536)         // 99328 -> occ 2

// ---------------------------------------------------------------------------
// k_prep: att (Bn/256 blocks) + wconv (256 blocks)
// ---------------------------------------------------------------------------
__global__ __launch_bounds__(256) void k_prep(const float* __restrict__ mem_W,
                                              const float* __restrict__ convt_w,
                                              const float* __restrict__ dv,
                                              const float* __restrict__ dW, int Bn) {
    int t = threadIdx.x;
    const int attBlocks = Bn / 256;

    if ((int)blockIdx.x >= attBlocks) {
        // ---------------- wconv ----------------
        int i = (blockIdx.x - attBlocks) * 256 + t;
        int c = i >> 6, k = i & 63;
        float s = 0.f;
        if (k < MEMD) {
            float w0 = convt_w[4], w1 = convt_w[3], w2 = convt_w[2], w3 = convt_w[1], w4 = convt_w[0];
            const float* p = mem_W + k * FEA + c;
            s = p[0]*w0 + p[1]*w1 + p[2]*w2 + p[3]*w3 + p[4]*w4;
        }
        __nv_bfloat16 h = __float2bfloat16_rn(s);
        __nv_bfloat16 l = __float2bfloat16_rn(s - __bfloat162float(h));
        g_Bh[i] = h;
        g_Bl[i] = l;
        return;
    }

    // ---------------- att ----------------
    __shared__ float s_dv[256][DATED + 1];
    __shared__ float s_dW[MEMD][DATED];
    __shared__ float s_out[256][MEMD + 1];

    int base = blockIdx.x * 256;

    for (int i = t; i < MEMD * DATED; i += 256) s_dW[i / DATED][i % DATED] = dW[i];
    for (int i = t; i < 256 * DATED; i += 256)
        s_dv[i / DATED][i % DATED] = dv[(size_t)base * DATED + i];
    __syncthreads();

    float sc[MEMD];
    float mx = -1e30f;
    #pragma unroll
    for (int m = 0; m < MEMD; m++) {
        float s = 0.f;
        #pragma unroll
        for (int d = 0; d < DATED; d++) s += s_dv[t][d] * s_dW[m][d];
        sc[m] = s;
        mx = fmaxf(mx, s);
    }
    float se = 0.f;
    #pragma unroll
    for (int m = 0; m < MEMD; m++) { float e = __expf(sc[m] - mx); sc[m] = e; se += e; }
    float inv = 1.f / se;
    float s2 = 0.f;
    #pragma unroll
    for (int m = 0; m < MEMD; m++) {
        float a = sc[m] * inv;
        float d = a - 0.0025f;
        float v = fmaxf(d, 0.f) * a / (fabsf(d) + 1e-12f);
        sc[m] = v;
        s2 += fabsf(v);
    }
    float inv2 = 1.f / (s2 + 1e-12f);
    #pragma unroll
    for (int m = 0; m < MEMD; m++) s_out[t][m] = sc[m] * inv2;
    __syncthreads();

    for (int i = t; i < 256 * KPAD; i += 256) {
        int r = i >> 6, k = i & 63;
        float a = (k < MEMD) ? s_out[r][k] : 0.f;
        __nv_bfloat16 h = __float2bfloat16_rn(a);
        __nv_bfloat16 l = __float2bfloat16_rn(a - __bfloat162float(h));
        size_t gi = (size_t)base * KPAD + i;
        g_atth[gi] = h;
        g_attl[gi] = l;
    }
}

// ---------------------------------------------------------------------------
// stage one B col-block (hi+lo, 32KB) into smem buffer via cp.async
// ---------------------------------------------------------------------------
__device__ __forceinline__ void stage_B(uint32_t sb, int cb, int buf, int t) {
    #pragma unroll
    for (int j = 0; j < 8; j++) {
        int i = t + j * 256;
        int term = i >> 10, rem = i & 1023, r = rem >> 3, ch = rem & 7;
        const __nv_bfloat16* src = (term ? g_Bl : g_Bh) + (size_t)(cb * 128 + r) * KPAD + ch * 8;
        cp16(sb + OFF_B + buf * 32768 + term * 16384 + swz((uint32_t)r, (uint32_t)(ch * 16)), src);
    }
}

// ---------------------------------------------------------------------------
// k_main: CTA = 128 rows, 256 threads, grid = Bn/128 = 256 (single wave).
//   phase A: own-row gates, fc weights in REGISTERS, 2-row interleaved LDG
//   phase B: R9-proven 3-term bf16 mma.sync GEMM + fused epilogue
// ---------------------------------------------------------------------------
__global__ __launch_bounds__(256, 2) void k_main(const float* __restrict__ x,
                                                 const float* __restrict__ fcw,
                                                 const float* __restrict__ fcwb,
                                                 const float* __restrict__ fcb,
                                                 const float* __restrict__ fcbb,
                                                 float* __restrict__ out, int Bn) {
    extern __shared__ char smem[];
    const uint32_t sb = smem_u32(smem);
    const int t = threadIdx.x;
    const int warp = t >> 5, lane = t & 31;
    const int rowBase = blockIdx.x * 128;

    float* s_wt = (float*)(smem + OFF_WT);
    float* s_bs = (float*)(smem + OFF_BS);

    // group 0: A (att) tile;  groups 1,2: first two B col-blocks
    #pragma unroll
    for (int j = 0; j < 8; j++) {
        int i = t + j * 256;
        int term = i >> 10, rem = i & 1023, r = rem >> 3, ch = rem & 7;
        const __nv_bfloat16* src = (term ? g_attl : g_atth) + (size_t)(rowBase + r) * KPAD + ch * 8;
        cp16(sb + OFF_A + term * 16384 + swz((uint32_t)r, (uint32_t)(ch * 16)), src);
    }
    CP_COMMIT();
    stage_B(sb, 0, 0, t); CP_COMMIT();
    stage_B(sb, 1, 1, t); CP_COMMIT();

    // ---- phase A: gates for own 128 rows; fc weights in registers ----
    {
        float4 fwr[8], fbr[8];
        #pragma unroll
        for (int j = 0; j < 8; j++) {
            fwr[j] = ((const float4*)fcw)[lane + 32 * j];
            fbr[j] = ((const float4*)fcb)[lane + 32 * j];
        }
        float fwb = fcwb[0], fbb = fcbb[0];

        // 8 warps x 16 rows, 2-row interleave (16 LDG.128 in flight)
        #pragma unroll 1
        for (int rr = 0; rr < 8; rr++) {
            int r0 = warp * 16 + rr * 2;
            const float4* x0 = (const float4*)(x + (size_t)(rowBase + r0) * LREF);
            const float4* x1 = (const float4*)(x + (size_t)(rowBase + r0 + 1) * LREF);
            float dw0 = 0.f, db0 = 0.f, dw1 = 0.f, db1 = 0.f;
            #pragma unroll
            for (int j = 0; j < 8; j++) {
                float4 v0 = x0[lane + 32 * j];
                float4 v1 = x1[lane + 32 * j];
                dw0 += v0.x*fwr[j].x + v0.y*fwr[j].y + v0.z*fwr[j].z + v0.w*fwr[j].w;
                db0 += v0.x*fbr[j].x + v0.y*fbr[j].y + v0.z*fbr[j].z + v0.w*fbr[j].w;
                dw1 += v1.x*fwr[j].x + v1.y*fwr[j].y + v1.z*fwr[j].z + v1.w*fwr[j].w;
                db1 += v1.x*fbr[j].x + v1.y*fbr[j].y + v1.z*fbr[j].z + v1.w*fbr[j].w;
            }
            #pragma unroll
            for (int o = 16; o; o >>= 1) {
                dw0 += __shfl_xor_sync(0xffffffffu, dw0, o);
                db0 += __shfl_xor_sync(0xffffffffu, db0, o);
                dw1 += __shfl_xor_sync(0xffffffffu, dw1, o);
                db1 += __shfl_xor_sync(0xffffffffu, db1, o);
            }
            if (lane == 0) {
                int row = rowBase + r0;
                float wt = tanhf(dw0 + fwb) * 0.5f + 1.0f;
                float bs = tanhf(db0 + fbb) * 0.5f;
                s_wt[r0] = wt;  s_bs[r0] = bs;
                out[(size_t)Bn * LREF + row]      = wt;
                out[(size_t)Bn * LREF + Bn + row] = bs;
                wt = tanhf(dw1 + fwb) * 0.5f + 1.0f;
                bs = tanhf(db1 + fbb) * 0.5f;
                s_wt[r0 + 1] = wt;  s_bs[r0 + 1] = bs;
                out[(size_t)Bn * LREF + row + 1]      = wt;
                out[(size_t)Bn * LREF + Bn + row + 1] = bs;
            }
        }
    }

    CP_WAIT(2);          // A tile done (B copies may still be in flight)
    __syncthreads();

    // ---- A fragments into registers (once) ----
    uint32_t ah[4][4], al[4][4];
    {
        uint32_t ra = (uint32_t)(warp * 16 + (lane & 15));
        uint32_t cbase = (uint32_t)((lane >> 4) * 16);
        #pragma unroll
        for (int ks = 0; ks < 4; ks++) {
            uint32_t off = swz(ra, cbase + ks * 32);
            ldsm_x4(ah[ks], sb + OFF_A + off);
            ldsm_x4(al[ks], sb + OFF_A + 16384 + off);
        }
    }

    // per-thread epilogue coords
    const int grp = lane >> 2, qc = lane & 3;
    const float wt0 = s_wt[warp * 16 + grp],     bs0 = s_bs[warp * 16 + grp];
    const float wt1 = s_wt[warp * 16 + grp + 8], bs1 = s_bs[warp * 16 + grp + 8];

    // B-fragment per-lane constants
    const uint32_t rb  = (uint32_t)((lane & 7) + ((lane >> 4) << 3));
    const uint32_t ccb = (uint32_t)(((lane >> 3) & 1) * 16);
    const uint32_t xv  = (uint32_t)((lane & 7) << 4);

    // ---- GEMM over 8 col-blocks, double-buffered cp.async ----
    for (int cb = 0; cb < 8; cb++) {
        CP_WAIT(1);          // B(cb) arrived
        __syncthreads();
        const uint32_t bbase = sb + OFF_B + (uint32_t)((cb & 1) * 32768);

        float acc[16][4];
        #pragma unroll
        for (int nt = 0; nt < 16; nt++) {
            acc[nt][0] = 0.f; acc[nt][1] = 0.f; acc[nt][2] = 0.f; acc[nt][3] = 0.f;
        }

        #pragma unroll
        for (int ks = 0; ks < 4; ks++) {
            const uint32_t col = (ccb + (uint32_t)(ks * 32)) ^ xv;
            #pragma unroll
            for (int ntp = 0; ntp < 8; ntp++) {
                uint32_t addr = bbase + (uint32_t)((ntp * 16) + rb) * 128u + col;
                uint32_t bh[4], bl[4];
                ldsm_x4(bh, addr);
                ldsm_x4(bl, addr + 16384);
                mma_bf16(acc[2*ntp],     ah[ks], bh);
                mma_bf16(acc[2*ntp + 1], ah[ks], bh + 2);
                mma_bf16(acc[2*ntp],     al[ks], bh);
                mma_bf16(acc[2*ntp + 1], al[ks], bh + 2);
                mma_bf16(acc[2*ntp],     ah[ks], bl);
                mma_bf16(acc[2*ntp + 1], ah[ks], bl + 2);
            }
        }

        // fused epilogue: out = acc*wt + bs
        {
            size_t r0 = (size_t)(rowBase + warp * 16 + grp) * LREF;
            size_t r1 = r0 + 8 * LREF;
            int colBase = cb * 128 + qc * 2;
            #pragma unroll
            for (int nt = 0; nt < 16; nt++) {
                int col = colBase + nt * 8;
                *(float2*)&out[r0 + col] =
                    make_float2(acc[nt][0] * wt0 + bs0, acc[nt][1] * wt0 + bs0);
                *(float2*)&out[r1 + col] =
                    make_float2(acc[nt][2] * wt1 + bs1, acc[nt][3] * wt1 + bs1);
            }
        }

        __syncthreads();                       // all readers done with buf(cb)
        if (cb + 2 < 8) stage_B(sb, cb + 2, cb & 1, t);
        CP_COMMIT();                           // commit (possibly empty) group
    }
}

// ---------------------------------------------------------------------------
extern "C" void kernel_launch(void* const* d_in, const int* in_sizes, int n_in,
                              void* d_out, int out_size) {
    const float* x    = (const float*)d_in[0];
    const float* dv   = (const float*)d_in[1];
    // d_in[2] = conv_w (dead in reference)
    const float* ctw  = (const float*)d_in[3];
    const float* memW = (const float*)d_in[4];
    const float* dW   = (const float*)d_in[5];
    const float* fcw  = (const float*)d_in[6];
    const float* fcwb = (const float*)d_in[7];
    const float* fcb  = (const float*)d_in[8];
    const float* fcbb = (const float*)d_in[9];
    float* out = (float*)d_out;

    int Bn = in_sizes[0] / LREF;

    cudaFuncSetAttribute(k_main, cudaFuncAttributeMaxDynamicSharedMemorySize, SMEM_SZ);

    k_prep<<<Bn / 256 + 256, 256>>>(memW, ctw, dv, dW, Bn);
    k_main<<<Bn / 128, 256, SMEM_SZ>>>(x, fcw, fcwb, fcb, fcbb, out, Bn);
}

// round 14
// speedup vs baseline: 4.5470x; 1.3376x over previous
#include <cuda_runtime.h>
#include <cuda_bf16.h>
#include <cstdint>

#define LREF  1024
#define FEA   1028
#define MEMD  50
#define KPAD  64
#define DATED 32
#define MAXB  32768

// ------------------- device scratch (allocation-free rule) -------------------
__device__ __nv_bfloat16 g_atth[MAXB * KPAD];   // att hi  [row][k] padded
__device__ __nv_bfloat16 g_attl[MAXB * KPAD];   // att lo
__device__ __nv_bfloat16 g_Bh[LREF * KPAD];     // Wfold^T hi [col][k]
__device__ __nv_bfloat16 g_Bl[LREF * KPAD];     // Wfold^T lo

// ------------------- helpers -------------------
__device__ __forceinline__ uint32_t smem_u32(const void* p) {
    uint32_t a;
    asm("{ .reg .u64 t; cvta.to.shared.u64 t, %1; cvt.u32.u64 %0, t; }" : "=r"(a) : "l"(p));
    return a;
}
__device__ __forceinline__ void ldsm_x4(uint32_t* r, uint32_t a) {
    asm volatile("ldmatrix.sync.aligned.m8n8.x4.shared.b16 {%0,%1,%2,%3}, [%4];"
                 : "=r"(r[0]), "=r"(r[1]), "=r"(r[2]), "=r"(r[3]) : "r"(a));
}
__device__ __forceinline__ void mma_bf16(float* d, const uint32_t* a, const uint32_t* b) {
    asm volatile(
        "mma.sync.aligned.m16n8k16.row.col.f32.bf16.bf16.f32 "
        "{%0,%1,%2,%3}, {%4,%5,%6,%7}, {%8,%9}, {%0,%1,%2,%3};"
        : "+f"(d[0]), "+f"(d[1]), "+f"(d[2]), "+f"(d[3])
        : "r"(a[0]), "r"(a[1]), "r"(a[2]), "r"(a[3]), "r"(b[0]), "r"(b[1]));
}
__device__ __forceinline__ void cp16(uint32_t dst, const void* src) {
    asm volatile("cp.async.cg.shared.global [%0], [%1], 16;" :: "r"(dst), "l"(src) : "memory");
}
#define CP_COMMIT() asm volatile("cp.async.commit_group;" ::: "memory")
#define CP_WAIT(n)  asm volatile("cp.async.wait_group %0;" :: "n"(n) : "memory")

// XOR swizzle for 128B-row tiles: conflict-free ldmatrix + conflict-free stores
__device__ __forceinline__ uint32_t swz(uint32_t r, uint32_t c) {
    return r * 128u + (c ^ ((r & 7u) << 4));
}

// k_main smem layout (bytes): CTA = 64 rows
#define OFF_WT  0                       // 256B
#define OFF_BS  256                     // 256B
#define OFF_A   512                     // hi 8KB + lo 8KB
#define OFF_B   16896                   // 2 bufs x 32KB
#define SMEM_SZ (OFF_B + 65536)         // 82432 -> occ 2

// ---------------------------------------------------------------------------
// k_prep: att (Bn/256 blocks) + wconv (256 blocks)
// ---------------------------------------------------------------------------
__global__ __launch_bounds__(256) void k_prep(const float* __restrict__ mem_W,
                                              const float* __restrict__ convt_w,
                                              const float* __restrict__ dv,
                                              const float* __restrict__ dW, int Bn) {
    int t = threadIdx.x;
    const int attBlocks = Bn / 256;

    if ((int)blockIdx.x >= attBlocks) {
        // ---------------- wconv ----------------
        int i = (blockIdx.x - attBlocks) * 256 + t;
        int c = i >> 6, k = i & 63;
        float s = 0.f;
        if (k < MEMD) {
            float w0 = convt_w[4], w1 = convt_w[3], w2 = convt_w[2], w3 = convt_w[1], w4 = convt_w[0];
            const float* p = mem_W + k * FEA + c;
            s = p[0]*w0 + p[1]*w1 + p[2]*w2 + p[3]*w3 + p[4]*w4;
        }
        __nv_bfloat16 h = __float2bfloat16_rn(s);
        __nv_bfloat16 l = __float2bfloat16_rn(s - __bfloat162float(h));
        g_Bh[i] = h;
        g_Bl[i] = l;
        return;
    }

    // ---------------- att ----------------
    __shared__ float s_dv[256][DATED + 1];
    __shared__ float s_dW[MEMD][DATED];
    __shared__ float s_out[256][MEMD + 1];

    int base = blockIdx.x * 256;

    for (int i = t; i < MEMD * DATED; i += 256) s_dW[i / DATED][i % DATED] = dW[i];
    for (int i = t; i < 256 * DATED; i += 256)
        s_dv[i / DATED][i % DATED] = dv[(size_t)base * DATED + i];
    __syncthreads();

    float sc[MEMD];
    float mx = -1e30f;
    #pragma unroll
    for (int m = 0; m < MEMD; m++) {
        float s = 0.f;
        #pragma unroll
        for (int d = 0; d < DATED; d++) s += s_dv[t][d] * s_dW[m][d];
        sc[m] = s;
        mx = fmaxf(mx, s);
    }
    float se = 0.f;
    #pragma unroll
    for (int m = 0; m < MEMD; m++) { float e = __expf(sc[m] - mx); sc[m] = e; se += e; }
    float inv = 1.f / se;
    float s2 = 0.f;
    #pragma unroll
    for (int m = 0; m < MEMD; m++) {
        float a = sc[m] * inv;
        float d = a - 0.0025f;
        float v = fmaxf(d, 0.f) * a / (fabsf(d) + 1e-12f);
        sc[m] = v;
        s2 += fabsf(v);
    }
    float inv2 = 1.f / (s2 + 1e-12f);
    #pragma unroll
    for (int m = 0; m < MEMD; m++) s_out[t][m] = sc[m] * inv2;
    __syncthreads();

    for (int i = t; i < 256 * KPAD; i += 256) {
        int r = i >> 6, k = i & 63;
        float a = (k < MEMD) ? s_out[r][k] : 0.f;
        __nv_bfloat16 h = __float2bfloat16_rn(a);
        __nv_bfloat16 l = __float2bfloat16_rn(a - __bfloat162float(h));
        size_t gi = (size_t)base * KPAD + i;
        g_atth[gi] = h;
        g_attl[gi] = l;
    }
}

// ---------------------------------------------------------------------------
// stage one B col-block (hi+lo, 32KB) into smem buffer via cp.async
// ---------------------------------------------------------------------------
__device__ __forceinline__ void stage_B(uint32_t sb, int cb, int buf, int t) {
    #pragma unroll
    for (int j = 0; j < 8; j++) {
        int i = t + j * 256;
        int term = i >> 10, rem = i & 1023, r = rem >> 3, ch = rem & 7;
        const __nv_bfloat16* src = (term ? g_Bl : g_Bh) + (size_t)(cb * 128 + r) * KPAD + ch * 8;
        cp16(sb + OFF_B + buf * 32768 + term * 16384 + swz((uint32_t)r, (uint32_t)(ch * 16)), src);
    }
}

// ---------------------------------------------------------------------------
// k_main: CTA = 64 rows, 256 threads, grid = Bn/64 = 512 (1.7 waves, occ 2:
//   work-steal pipelines gate phase (DRAM read) against GEMM phase (write)).
//   Warp tile 16x64: wr = warp>>1 rows, wc = warp&1 cols -> B LDSM halved.
// ---------------------------------------------------------------------------
__global__ __launch_bounds__(256, 2) void k_main(const float* __restrict__ x,
                                                 const float* __restrict__ fcw,
                                                 const float* __restrict__ fcwb,
                                                 const float* __restrict__ fcb,
                                                 const float* __restrict__ fcbb,
                                                 float* __restrict__ out, int Bn) {
    extern __shared__ char smem[];
    const uint32_t sb = smem_u32(smem);
    const int t = threadIdx.x;
    const int warp = t >> 5, lane = t & 31;
    const int wr = warp >> 1, wc = warp & 1;
    const int rowBase = blockIdx.x * 64;

    float* s_wt = (float*)(smem + OFF_WT);
    float* s_bs = (float*)(smem + OFF_BS);

    // group 0: A (att) tile 16KB;  groups 1,2: first two B col-blocks
    #pragma unroll
    for (int j = 0; j < 4; j++) {
        int i = t + j * 256;
        int term = i >> 9, rem = i & 511, r = rem >> 3, ch = i & 7;
        const __nv_bfloat16* src = (term ? g_attl : g_atth) + (size_t)(rowBase + r) * KPAD + ch * 8;
        cp16(sb + OFF_A + term * 8192 + swz((uint32_t)r, (uint32_t)(ch * 16)), src);
    }
    CP_COMMIT();
    stage_B(sb, 0, 0, t); CP_COMMIT();
    stage_B(sb, 1, 1, t); CP_COMMIT();

    // ---- gate phase: 8 warps x 8 rows, fc weights in registers ----
    {
        float4 fwr[8], fbr[8];
        #pragma unroll
        for (int j = 0; j < 8; j++) {
            fwr[j] = ((const float4*)fcw)[lane + 32 * j];
            fbr[j] = ((const float4*)fcb)[lane + 32 * j];
        }
        float fwb = fcwb[0], fbb = fcbb[0];

        #pragma unroll 1
        for (int rr = 0; rr < 4; rr++) {
            int r0 = warp * 8 + rr * 2;
            const float4* x0 = (const float4*)(x + (size_t)(rowBase + r0) * LREF);
            const float4* x1 = (const float4*)(x + (size_t)(rowBase + r0 + 1) * LREF);
            float dw0 = 0.f, db0 = 0.f, dw1 = 0.f, db1 = 0.f;
            #pragma unroll
            for (int j = 0; j < 8; j++) {
                float4 v0 = x0[lane + 32 * j];
                float4 v1 = x1[lane + 32 * j];
                dw0 += v0.x*fwr[j].x + v0.y*fwr[j].y + v0.z*fwr[j].z + v0.w*fwr[j].w;
                db0 += v0.x*fbr[j].x + v0.y*fbr[j].y + v0.z*fbr[j].z + v0.w*fbr[j].w;
                dw1 += v1.x*fwr[j].x + v1.y*fwr[j].y + v1.z*fwr[j].z + v1.w*fwr[j].w;
                db1 += v1.x*fbr[j].x + v1.y*fbr[j].y + v1.z*fbr[j].z + v1.w*fbr[j].w;
            }
            #pragma unroll
            for (int o = 16; o; o >>= 1) {
                dw0 += __shfl_xor_sync(0xffffffffu, dw0, o);
                db0 += __shfl_xor_sync(0xffffffffu, db0, o);
                dw1 += __shfl_xor_sync(0xffffffffu, dw1, o);
                db1 += __shfl_xor_sync(0xffffffffu, db1, o);
            }
            if (lane == 0) {
                int row = rowBase + r0;
                float wt = tanhf(dw0 + fwb) * 0.5f + 1.0f;
                float bs = tanhf(db0 + fbb) * 0.5f;
                s_wt[r0] = wt;  s_bs[r0] = bs;
                out[(size_t)Bn * LREF + row]      = wt;
                out[(size_t)Bn * LREF + Bn + row] = bs;
                wt = tanhf(dw1 + fwb) * 0.5f + 1.0f;
                bs = tanhf(db1 + fbb) * 0.5f;
                s_wt[r0 + 1] = wt;  s_bs[r0 + 1] = bs;
                out[(size_t)Bn * LREF + row + 1]      = wt;
                out[(size_t)Bn * LREF + Bn + row + 1] = bs;
            }
        }
    }

    CP_WAIT(2);          // A tile done
    __syncthreads();     // A + all gates visible

    // ---- A fragments into registers (rows wr*16 .. +16, once) ----
    uint32_t ah[4][4], al[4][4];
    {
        uint32_t ra = (uint32_t)(wr * 16 + (lane & 15));
        uint32_t cbase = (uint32_t)((lane >> 4) * 16);
        #pragma unroll
        for (int ks = 0; ks < 4; ks++) {
            uint32_t off = swz(ra, cbase + ks * 32);
            ldsm_x4(ah[ks], sb + OFF_A + off);
            ldsm_x4(al[ks], sb + OFF_A + 8192 + off);
        }
    }

    // per-thread epilogue coords
    const int grp = lane >> 2, qc = lane & 3;
    const float wt0 = s_wt[wr * 16 + grp],     bs0 = s_bs[wr * 16 + grp];
    const float wt1 = s_wt[wr * 16 + grp + 8], bs1 = s_bs[wr * 16 + grp + 8];

    // B-fragment per-lane constants
    const uint32_t rb  = (uint32_t)((lane & 7) + ((lane >> 4) << 3));
    const uint32_t ccb = (uint32_t)(((lane >> 3) & 1) * 16);
    const uint32_t xv  = (uint32_t)((lane & 7) << 4);

    // ---- GEMM over 8 col-blocks, double-buffered cp.async ----
    for (int cb = 0; cb < 8; cb++) {
        CP_WAIT(1);          // B(cb) arrived
        __syncthreads();
        const uint32_t bbase = sb + OFF_B + (uint32_t)((cb & 1) * 32768);

        float acc[8][4];
        #pragma unroll
        for (int nt = 0; nt < 8; nt++) {
            acc[nt][0] = 0.f; acc[nt][1] = 0.f; acc[nt][2] = 0.f; acc[nt][3] = 0.f;
        }

        #pragma unroll
        for (int ks = 0; ks < 4; ks++) {
            const uint32_t col = (ccb + (uint32_t)(ks * 32)) ^ xv;
            #pragma unroll
            for (int ntp = 0; ntp < 4; ntp++) {
                uint32_t addr = bbase + (uint32_t)(wc * 64 + ntp * 16 + rb) * 128u + col;
                uint32_t bh[4], bl[4];
                ldsm_x4(bh, addr);
                ldsm_x4(bl, addr + 16384);
                mma_bf16(acc[2*ntp],     ah[ks], bh);
                mma_bf16(acc[2*ntp + 1], ah[ks], bh + 2);
                mma_bf16(acc[2*ntp],     al[ks], bh);
                mma_bf16(acc[2*ntp + 1], al[ks], bh + 2);
                mma_bf16(acc[2*ntp],     ah[ks], bl);
                mma_bf16(acc[2*ntp + 1], ah[ks], bl + 2);
            }
        }

        // fused epilogue: out = acc*wt + bs
        {
            size_t r0 = (size_t)(rowBase + wr * 16 + grp) * LREF;
            size_t r1 = r0 + 8 * LREF;
            int colBase = cb * 128 + wc * 64 + qc * 2;
            #pragma unroll
            for (int nt = 0; nt < 8; nt++) {
                int col = colBase + nt * 8;
                *(float2*)&out[r0 + col] =
                    make_float2(acc[nt][0] * wt0 + bs0, acc[nt][1] * wt0 + bs0);
                *(float2*)&out[r1 + col] =
                    make_float2(acc[nt][2] * wt1 + bs1, acc[nt][3] * wt1 + bs1);
            }
        }

        __syncthreads();                       // all readers done with buf(cb)
        if (cb + 2 < 8) stage_B(sb, cb + 2, cb & 1, t);
        CP_COMMIT();                           // commit (possibly empty) group
    }
}

// ---------------------------------------------------------------------------
extern "C" void kernel_launch(void* const* d_in, const int* in_sizes, int n_in,
                              void* d_out, int out_size) {
    const float* x    = (const float*)d_in[0];
    const float* dv   = (const float*)d_in[1];
    // d_in[2] = conv_w (dead in reference)
    const float* ctw  = (const float*)d_in[3];
    const float* memW = (const float*)d_in[4];
    const float* dW   = (const float*)d_in[5];
    const float* fcw  = (const float*)d_in[6];
    const float* fcwb = (const float*)d_in[7];
    const float* fcb  = (const float*)d_in[8];
    const float* fcbb = (const float*)d_in[9];
    float* out = (float*)d_out;

    int Bn = in_sizes[0] / LREF;

    cudaFuncSetAttribute(k_main, cudaFuncAttributeMaxDynamicSharedMemorySize, SMEM_SZ);

    k_prep<<<Bn / 256 + 256, 256>>>(memW, ctw, dv, dW, Bn);
    k_main<<<Bn / 64, 256, SMEM_SZ>>>(x, fcw, fcwb, fcb, fcbb, out, Bn);
}

// round 15
// speedup vs baseline: 4.9510x; 1.0889x over previous
#include <cuda_runtime.h>
#include <cuda_bf16.h>
#include <cstdint>

#define LREF  1024
#define FEA   1028
#define MEMD  50
#define KPAD  64
#define DATED 32
#define MAXB  32768

// ------------------- device scratch (allocation-free rule) -------------------
__device__ __nv_bfloat16 g_atth[MAXB * KPAD];   // att hi  [row][k] padded
__device__ __nv_bfloat16 g_attl[MAXB * KPAD];   // att lo
__device__ __nv_bfloat16 g_Bh[LREF * KPAD];     // Wfold^T bf16 [col][k]

// ------------------- helpers -------------------
__device__ __forceinline__ uint32_t smem_u32(const void* p) {
    uint32_t a;
    asm("{ .reg .u64 t; cvta.to.shared.u64 t, %1; cvt.u32.u64 %0, t; }" : "=r"(a) : "l"(p));
    return a;
}
__device__ __forceinline__ void ldsm_x4(uint32_t* r, uint32_t a) {
    asm volatile("ldmatrix.sync.aligned.m8n8.x4.shared.b16 {%0,%1,%2,%3}, [%4];"
                 : "=r"(r[0]), "=r"(r[1]), "=r"(r[2]), "=r"(r[3]) : "r"(a));
}
__device__ __forceinline__ void mma_bf16(float* d, const uint32_t* a, const uint32_t* b) {
    asm volatile(
        "mma.sync.aligned.m16n8k16.row.col.f32.bf16.bf16.f32 "
        "{%0,%1,%2,%3}, {%4,%5,%6,%7}, {%8,%9}, {%0,%1,%2,%3};"
        : "+f"(d[0]), "+f"(d[1]), "+f"(d[2]), "+f"(d[3])
        : "r"(a[0]), "r"(a[1]), "r"(a[2]), "r"(a[3]), "r"(b[0]), "r"(b[1]));
}
__device__ __forceinline__ void cp16(uint32_t dst, const void* src) {
    asm volatile("cp.async.cg.shared.global [%0], [%1], 16;" :: "r"(dst), "l"(src) : "memory");
}
#define CP_COMMIT() asm volatile("cp.async.commit_group;" ::: "memory")
#define CP_WAIT(n)  asm volatile("cp.async.wait_group %0;" :: "n"(n) : "memory")

// XOR swizzle for 128B-row tiles: conflict-free ldmatrix + conflict-free stores
__device__ __forceinline__ uint32_t swz(uint32_t r, uint32_t c) {
    return r * 128u + (c ^ ((r & 7u) << 4));
}

// k_main smem layout (bytes): CTA = 64 rows
#define OFF_WT  0                       // 256B
#define OFF_BS  256                     // 256B
#define OFF_FCW 512                     // 4KB
#define OFF_FCB 4608                    // 4KB
#define OFF_A   8704                    // hi 8KB + lo 8KB
#define OFF_B   25088                   // 2 bufs x 16KB (B single bf16)
#define SMEM_SZ (OFF_B + 2 * 16384)     // 57856 -> occ 3 (w/ 85 regs)

// ---------------------------------------------------------------------------
// k_prep: att (Bn/256 blocks) + wconv (256 blocks)
// ---------------------------------------------------------------------------
__global__ __launch_bounds__(256) void k_prep(const float* __restrict__ mem_W,
                                              const float* __restrict__ convt_w,
                                              const float* __restrict__ dv,
                                              const float* __restrict__ dW, int Bn) {
    int t = threadIdx.x;
    const int attBlocks = Bn / 256;

    if ((int)blockIdx.x >= attBlocks) {
        // ---------------- wconv ----------------
        int i = (blockIdx.x - attBlocks) * 256 + t;
        int c = i >> 6, k = i & 63;
        float s = 0.f;
        if (k < MEMD) {
            float w0 = convt_w[4], w1 = convt_w[3], w2 = convt_w[2], w3 = convt_w[1], w4 = convt_w[0];
            const float* p = mem_W + k * FEA + c;
            s = p[0]*w0 + p[1]*w1 + p[2]*w2 + p[3]*w3 + p[4]*w4;
        }
        g_Bh[i] = __float2bfloat16_rn(s);
        return;
    }

    // ---------------- att ----------------
    __shared__ float s_dv[256][DATED + 1];
    __shared__ float s_dW[MEMD][DATED];
    __shared__ float s_out[256][MEMD + 1];

    int base = blockIdx.x * 256;

    for (int i = t; i < MEMD * DATED; i += 256) s_dW[i / DATED][i % DATED] = dW[i];
    for (int i = t; i < 256 * DATED; i += 256)
        s_dv[i / DATED][i % DATED] = dv[(size_t)base * DATED + i];
    __syncthreads();

    float sc[MEMD];
    float mx = -1e30f;
    #pragma unroll
    for (int m = 0; m < MEMD; m++) {
        float s = 0.f;
        #pragma unroll
        for (int d = 0; d < DATED; d++) s += s_dv[t][d] * s_dW[m][d];
        sc[m] = s;
        mx = fmaxf(mx, s);
    }
    float se = 0.f;
    #pragma unroll
    for (int m = 0; m < MEMD; m++) { float e = __expf(sc[m] - mx); sc[m] = e; se += e; }
    float inv = 1.f / se;
    float s2 = 0.f;
    #pragma unroll
    for (int m = 0; m < MEMD; m++) {
        float a = sc[m] * inv;
        float d = a - 0.0025f;
        float v = fmaxf(d, 0.f) * a / (fabsf(d) + 1e-12f);
        sc[m] = v;
        s2 += fabsf(v);
    }
    float inv2 = 1.f / (s2 + 1e-12f);
    #pragma unroll
    for (int m = 0; m < MEMD; m++) s_out[t][m] = sc[m] * inv2;
    __syncthreads();

    for (int i = t; i < 256 * KPAD; i += 256) {
        int r = i >> 6, k = i & 63;
        float a = (k < MEMD) ? s_out[r][k] : 0.f;
        __nv_bfloat16 h = __float2bfloat16_rn(a);
        __nv_bfloat16 l = __float2bfloat16_rn(a - __bfloat162float(h));
        size_t gi = (size_t)base * KPAD + i;
        g_atth[gi] = h;
        g_attl[gi] = l;
    }
}

// ---------------------------------------------------------------------------
// stage one B col-block (16KB, single bf16) into smem buffer via cp.async
// ---------------------------------------------------------------------------
__device__ __forceinline__ void stage_B(uint32_t sb, int cb, int buf, int t) {
    #pragma unroll
    for (int j = 0; j < 4; j++) {
        int i = t + j * 256;
        int r = i >> 3, ch = i & 7;
        const __nv_bfloat16* src = g_Bh + (size_t)(cb * 128 + r) * KPAD + ch * 8;
        cp16(sb + OFF_B + buf * 16384 + swz((uint32_t)r, (uint32_t)(ch * 16)), src);
    }
}

// ---------------------------------------------------------------------------
// k_main: CTA = 64 rows, 256 threads, grid = Bn/64 = 512, occ 3 (1.15 waves).
//   gate phase (fc in smem) then 2-term-split GEMM (A hi/lo, B single bf16).
//   Warp tile 16x64: wr = warp>>1 rows, wc = warp&1 cols.
// ---------------------------------------------------------------------------
__global__ __launch_bounds__(256, 3) void k_main(const float* __restrict__ x,
                                                 const float* __restrict__ fcw,
                                                 const float* __restrict__ fcwb,
                                                 const float* __restrict__ fcb,
                                                 const float* __restrict__ fcbb,
                                                 float* __restrict__ out, int Bn) {
    extern __shared__ char smem[];
    const uint32_t sb = smem_u32(smem);
    const int t = threadIdx.x;
    const int warp = t >> 5, lane = t & 31;
    const int wr = warp >> 1, wc = warp & 1;
    const int rowBase = blockIdx.x * 64;

    float* s_wt = (float*)(smem + OFF_WT);
    float* s_bs = (float*)(smem + OFF_BS);

    // group 0: A (att) tile 16KB + fc weights
    #pragma unroll
    for (int j = 0; j < 4; j++) {
        int i = t + j * 256;
        int term = i >> 9, rem = i & 511, r = rem >> 3, ch = i & 7;
        const __nv_bfloat16* src = (term ? g_attl : g_atth) + (size_t)(rowBase + r) * KPAD + ch * 8;
        cp16(sb + OFF_A + term * 8192 + swz((uint32_t)r, (uint32_t)(ch * 16)), src);
    }
    cp16(sb + OFF_FCW + t * 16, fcw + t * 4);
    cp16(sb + OFF_FCB + t * 16, fcb + t * 4);
    CP_COMMIT();
    stage_B(sb, 0, 0, t); CP_COMMIT();
    stage_B(sb, 1, 1, t); CP_COMMIT();

    CP_WAIT(2);          // A + fc staged
    __syncthreads();

    // ---- gate phase: 8 warps x 8 rows, fc weights from smem ----
    {
        const float4* fw4 = (const float4*)(smem + OFF_FCW);
        const float4* fb4 = (const float4*)(smem + OFF_FCB);
        float fwb = fcwb[0], fbb = fcbb[0];

        #pragma unroll 1
        for (int rr = 0; rr < 4; rr++) {
            int r0 = warp * 8 + rr * 2;
            const float4* x0 = (const float4*)(x + (size_t)(rowBase + r0) * LREF);
            const float4* x1 = (const float4*)(x + (size_t)(rowBase + r0 + 1) * LREF);
            float dw0 = 0.f, db0 = 0.f, dw1 = 0.f, db1 = 0.f;
            #pragma unroll
            for (int j = 0; j < 8; j++) {
                float4 v0 = x0[lane + 32 * j];
                float4 v1 = x1[lane + 32 * j];
                float4 a = fw4[lane + 32 * j];
                float4 b = fb4[lane + 32 * j];
                dw0 += v0.x*a.x + v0.y*a.y + v0.z*a.z + v0.w*a.w;
                db0 += v0.x*b.x + v0.y*b.y + v0.z*b.z + v0.w*b.w;
                dw1 += v1.x*a.x + v1.y*a.y + v1.z*a.z + v1.w*a.w;
                db1 += v1.x*b.x + v1.y*b.y + v1.z*b.z + v1.w*b.w;
            }
            #pragma unroll
            for (int o = 16; o; o >>= 1) {
                dw0 += __shfl_xor_sync(0xffffffffu, dw0, o);
                db0 += __shfl_xor_sync(0xffffffffu, db0, o);
                dw1 += __shfl_xor_sync(0xffffffffu, dw1, o);
                db1 += __shfl_xor_sync(0xffffffffu, db1, o);
            }
            if (lane == 0) {
                int row = rowBase + r0;
                float wt = tanhf(dw0 + fwb) * 0.5f + 1.0f;
                float bs = tanhf(db0 + fbb) * 0.5f;
                s_wt[r0] = wt;  s_bs[r0] = bs;
                out[(size_t)Bn * LREF + row]      = wt;
                out[(size_t)Bn * LREF + Bn + row] = bs;
                wt = tanhf(dw1 + fwb) * 0.5f + 1.0f;
                bs = tanhf(db1 + fbb) * 0.5f;
                s_wt[r0 + 1] = wt;  s_bs[r0 + 1] = bs;
                out[(size_t)Bn * LREF + row + 1]      = wt;
                out[(size_t)Bn * LREF + Bn + row + 1] = bs;
            }
        }
    }
    __syncthreads();     // gates visible

    // ---- A fragments into registers (rows wr*16 .. +16, once) ----
    uint32_t ah[4][4], al[4][4];
    {
        uint32_t ra = (uint32_t)(wr * 16 + (lane & 15));
        uint32_t cbase = (uint32_t)((lane >> 4) * 16);
        #pragma unroll
        for (int ks = 0; ks < 4; ks++) {
            uint32_t off = swz(ra, cbase + ks * 32);
            ldsm_x4(ah[ks], sb + OFF_A + off);
            ldsm_x4(al[ks], sb + OFF_A + 8192 + off);
        }
    }

    // per-thread epilogue coords
    const int grp = lane >> 2, qc = lane & 3;
    const float wt0 = s_wt[wr * 16 + grp],     bs0 = s_bs[wr * 16 + grp];
    const float wt1 = s_wt[wr * 16 + grp + 8], bs1 = s_bs[wr * 16 + grp + 8];

    // B-fragment per-lane constants
    const uint32_t rb  = (uint32_t)((lane & 7) + ((lane >> 4) << 3));
    const uint32_t ccb = (uint32_t)(((lane >> 3) & 1) * 16);
    const uint32_t xv  = (uint32_t)((lane & 7) << 4);

    // ---- GEMM over 8 col-blocks, double-buffered cp.async ----
    for (int cb = 0; cb < 8; cb++) {
        CP_WAIT(1);          // B(cb) arrived
        __syncthreads();
        const uint32_t bbase = sb + OFF_B + (uint32_t)((cb & 1) * 16384);

        float acc[8][4];
        #pragma unroll
        for (int nt = 0; nt < 8; nt++) {
            acc[nt][0] = 0.f; acc[nt][1] = 0.f; acc[nt][2] = 0.f; acc[nt][3] = 0.f;
        }

        #pragma unroll
        for (int ks = 0; ks < 4; ks++) {
            const uint32_t col = (ccb + (uint32_t)(ks * 32)) ^ xv;
            #pragma unroll
            for (int ntp = 0; ntp < 4; ntp++) {
                uint32_t addr = bbase + (uint32_t)(wc * 64 + ntp * 16 + rb) * 128u + col;
                uint32_t bh[4];
                ldsm_x4(bh, addr);
                mma_bf16(acc[2*ntp],     ah[ks], bh);
                mma_bf16(acc[2*ntp],     al[ks], bh);
                mma_bf16(acc[2*ntp + 1], ah[ks], bh + 2);
                mma_bf16(acc[2*ntp + 1], al[ks], bh + 2);
            }
        }

        // fused epilogue: out = acc*wt + bs
        {
            size_t r0 = (size_t)(rowBase + wr * 16 + grp) * LREF;
            size_t r1 = r0 + 8 * LREF;
            int colBase = cb * 128 + wc * 64 + qc * 2;
            #pragma unroll
            for (int nt = 0; nt < 8; nt++) {
                int col = colBase + nt * 8;
                *(float2*)&out[r0 + col] =
                    make_float2(acc[nt][0] * wt0 + bs0, acc[nt][1] * wt0 + bs0);
                *(float2*)&out[r1 + col] =
                    make_float2(acc[nt][2] * wt1 + bs1, acc[nt][3] * wt1 + bs1);
            }
        }

        __syncthreads();                       // all readers done with buf(cb)
        if (cb + 2 < 8) stage_B(sb, cb + 2, cb & 1, t);
        CP_COMMIT();                           // commit (possibly empty) group
    }
}

// ---------------------------------------------------------------------------
extern "C" void kernel_launch(void* const* d_in, const int* in_sizes, int n_in,
                              void* d_out, int out_size) {
    const float* x    = (const float*)d_in[0];
    const float* dv   = (const float*)d_in[1];
    // d_in[2] = conv_w (dead in reference)
    const float* ctw  = (const float*)d_in[3];
    const float* memW = (const float*)d_in[4];
    const float* dW   = (const float*)d_in[5];
    const float* fcw  = (const float*)d_in[6];
    const float* fcwb = (const float*)d_in[7];
    const float* fcb  = (const float*)d_in[8];
    const float* fcbb = (const float*)d_in[9];
    float* out = (float*)d_out;

    int Bn = in_sizes[0] / LREF;

    cudaFuncSetAttribute(k_main, cudaFuncAttributeMaxDynamicSharedMemorySize, SMEM_SZ);

    k_prep<<<Bn / 256 + 256, 256>>>(memW, ctw, dv, dW, Bn);
    k_main<<<Bn / 64, 256, SMEM_SZ>>>(x, fcw, fcwb, fcb, fcbb, out, Bn);
}